// round 1
// baseline (speedup 1.0000x reference)
#include <cuda_runtime.h>
#include <math.h>
#include <stddef.h>

// Problem constants (fixed by the reference: B=32, T=D=256)
#define BB 32
#define TT 256
#define DD 256
#define EPSF 1e-18f

// -------- scratch (device globals; no allocation allowed) --------
__device__ float g_w1[BB * TT];   // rsqrt(colsum(back_AF) + eps)   [j,s]
__device__ float g_w2[BB * TT];   // rsqrt(colsum(back_VF) + eps)   [j,s]
__device__ float g_vi1[BB];       // rsqrt(frob2(back_VF_i) + eps)
__device__ float g_vi2[BB];       // rsqrt(frob2(back_AF_i) + eps)
__device__ float g_R1[TT * DD];   // Atil[s,d] = sum_j w1[j,s]*AF[j,s,d]
__device__ float g_R2[TT * DD];   // Vtil[s,d] = sum_j w2[j,s]*VF[j,s,d]

// ============================================================
// Kernel 1: per-column sums of squares + Frobenius norms
// grid = 64 (2 matrices x 32 batch), 256 threads (one per column s)
// ============================================================
__global__ void stats_kernel(const float* __restrict__ VF,
                             const float* __restrict__ AF) {
    int i   = blockIdx.x & 31;
    int isA = blockIdx.x >> 5;
    const float* X = isA ? AF : VF;
    int s = threadIdx.x;

    const float* base = X + (size_t)i * TT * DD + s;
    float acc = 0.f;
#pragma unroll 8
    for (int t = 0; t < TT; ++t) {
        float v = base[(size_t)t * DD];
        acc += v * v;
    }
    float w = rsqrtf(acc + EPSF);
    if (isA) g_w1[i * TT + s] = w;   // colnorm of AF -> used in direction 1
    else     g_w2[i * TT + s] = w;   // colnorm of VF -> used in direction 2

    __shared__ float sh[256];
    sh[s] = acc;
    __syncthreads();
    for (int off = 128; off > 0; off >>= 1) {
        if (s < off) sh[s] += sh[s + off];
        __syncthreads();
    }
    if (s == 0) {
        float vi = rsqrtf(sh[0] + EPSF);
        if (isA) g_vi2[i] = vi;      // frob of AF -> direction 2 anchor norm
        else     g_vi1[i] = vi;      // frob of VF -> direction 1 anchor norm
    }
}

// ============================================================
// Kernel 2: fold the j-sum into one matrix per direction
// grid = (256, 2), 256 threads (one per d)
// ============================================================
__global__ void build_kernel(const float* __restrict__ VF,
                             const float* __restrict__ AF) {
    int s   = blockIdx.x;
    int dir = blockIdx.y;                 // 0: R1 from AF/w1, 1: R2 from VF/w2
    int d   = threadIdx.x;
    const float* X = dir ? VF : AF;
    const float* w = dir ? g_w2 : g_w1;

    float acc = 0.f;
#pragma unroll
    for (int j = 0; j < BB; ++j)
        acc += w[j * TT + s] * X[((size_t)j * TT + s) * DD + d];

    if (dir) g_R2[s * DD + d] = acc;
    else     g_R1[s * DD + d] = acc;
}

// ============================================================
// Kernel 3: fused quad-GEMM + epilogue
//   G1 = V_i @ R1^T, H1 = V_i @ A_i^T, G2 = A_i @ R2^T, H2 = A_i @ V_i^T
//   out[i,t,s] = -( log(32 + vi1*(G1 - w1[i,s]*H1))
//               +  log(32 + vi2*(G2 - w2[i,s]*H2)) )
// BM=BN=64, BK=16, 256 threads, 4x4 per thread, 4 accumulator sets.
// ============================================================
#define BM 64
#define BN 64
#define BK 16
#define LDP 68   // padded leading dim (68*4B stride: keeps float4 reads aligned)

__global__ void __launch_bounds__(256, 2)
main_kernel(const float* __restrict__ VF,
            const float* __restrict__ AF,
            float* __restrict__ out) {
    const int i  = blockIdx.z;
    const int t0 = blockIdx.y * BM;
    const int s0 = blockIdx.x * BN;

    __shared__ float sLV[BK * LDP];
    __shared__ float sLA[BK * LDP];
    __shared__ float sR1[BK * LDP];
    __shared__ float sRA[BK * LDP];
    __shared__ float sR2[BK * LDP];
    __shared__ float sRV[BK * LDP];

    const int tid = threadIdx.x;
    const int r   = tid >> 2;         // 0..63  (tile row)
    const int c   = (tid & 3) * 4;    // 0,4,8,12 (k-col start)
    const int ty  = tid >> 4;         // 0..15
    const int tx  = tid & 15;         // 0..15

    const float* pLV = VF + ((size_t)(i * TT + t0)) * DD;
    const float* pLA = AF + ((size_t)(i * TT + t0)) * DD;
    const float* pR1 = g_R1 + (size_t)s0 * DD;
    const float* pRA = AF + ((size_t)(i * TT + s0)) * DD;
    const float* pR2 = g_R2 + (size_t)s0 * DD;
    const float* pRV = VF + ((size_t)(i * TT + s0)) * DD;

    float acc1[4][4] = {}, acc2[4][4] = {}, acc3[4][4] = {}, acc4[4][4] = {};

    for (int k0 = 0; k0 < DD; k0 += BK) {
        // load 6 tiles of [64 rows x 16 k], stored transposed [k][row]
        const size_t goff = (size_t)r * DD + k0 + c;
        float4 v;
        v = *(const float4*)(pLV + goff);
        sLV[(c + 0) * LDP + r] = v.x; sLV[(c + 1) * LDP + r] = v.y;
        sLV[(c + 2) * LDP + r] = v.z; sLV[(c + 3) * LDP + r] = v.w;
        v = *(const float4*)(pLA + goff);
        sLA[(c + 0) * LDP + r] = v.x; sLA[(c + 1) * LDP + r] = v.y;
        sLA[(c + 2) * LDP + r] = v.z; sLA[(c + 3) * LDP + r] = v.w;
        v = *(const float4*)(pR1 + goff);
        sR1[(c + 0) * LDP + r] = v.x; sR1[(c + 1) * LDP + r] = v.y;
        sR1[(c + 2) * LDP + r] = v.z; sR1[(c + 3) * LDP + r] = v.w;
        v = *(const float4*)(pRA + goff);
        sRA[(c + 0) * LDP + r] = v.x; sRA[(c + 1) * LDP + r] = v.y;
        sRA[(c + 2) * LDP + r] = v.z; sRA[(c + 3) * LDP + r] = v.w;
        v = *(const float4*)(pR2 + goff);
        sR2[(c + 0) * LDP + r] = v.x; sR2[(c + 1) * LDP + r] = v.y;
        sR2[(c + 2) * LDP + r] = v.z; sR2[(c + 3) * LDP + r] = v.w;
        v = *(const float4*)(pRV + goff);
        sRV[(c + 0) * LDP + r] = v.x; sRV[(c + 1) * LDP + r] = v.y;
        sRV[(c + 2) * LDP + r] = v.z; sRV[(c + 3) * LDP + r] = v.w;
        __syncthreads();

#pragma unroll
        for (int kk = 0; kk < BK; ++kk) {
            const int ao = kk * LDP + ty * 4;
            const int bo = kk * LDP + tx * 4;
            float4 aV4 = *(const float4*)&sLV[ao];
            float4 aA4 = *(const float4*)&sLA[ao];
            float4 b14 = *(const float4*)&sR1[bo];
            float4 b24 = *(const float4*)&sRA[bo];
            float4 b34 = *(const float4*)&sR2[bo];
            float4 b44 = *(const float4*)&sRV[bo];
            float aV[4] = {aV4.x, aV4.y, aV4.z, aV4.w};
            float aA[4] = {aA4.x, aA4.y, aA4.z, aA4.w};
            float b1[4] = {b14.x, b14.y, b14.z, b14.w};
            float b2[4] = {b24.x, b24.y, b24.z, b24.w};
            float b3[4] = {b34.x, b34.y, b34.z, b34.w};
            float b4[4] = {b44.x, b44.y, b44.z, b44.w};
#pragma unroll
            for (int m = 0; m < 4; ++m) {
#pragma unroll
                for (int n = 0; n < 4; ++n) {
                    acc1[m][n] += aV[m] * b1[n];
                    acc2[m][n] += aV[m] * b2[n];
                    acc3[m][n] += aA[m] * b3[n];
                    acc4[m][n] += aA[m] * b4[n];
                }
            }
        }
        __syncthreads();
    }

    // epilogue
    const float vi1 = g_vi1[i];
    const float vi2 = g_vi2[i];
    float w1s[4], w2s[4];
#pragma unroll
    for (int n = 0; n < 4; ++n) {
        int s = s0 + tx * 4 + n;
        w1s[n] = g_w1[i * TT + s];
        w2s[n] = g_w2[i * TT + s];
    }
#pragma unroll
    for (int m = 0; m < 4; ++m) {
        int t = t0 + ty * 4 + m;
        float4 o;
        float res[4];
#pragma unroll
        for (int n = 0; n < 4; ++n) {
            // down = (B-1) + vi*(G - w*H); rows = log(1 + down)
            float d1 = (float)(BB - 1) + vi1 * (acc1[m][n] - w1s[n] * acc2[m][n]);
            float d2 = (float)(BB - 1) + vi2 * (acc3[m][n] - w2s[n] * acc4[m][n]);
            res[n] = -(logf(1.0f + d1) + logf(1.0f + d2));
        }
        o.x = res[0]; o.y = res[1]; o.z = res[2]; o.w = res[3];
        *(float4*)&out[((size_t)(i * TT + t)) * TT + s0 + tx * 4] = o;
    }
}

// ============================================================
extern "C" void kernel_launch(void* const* d_in, const int* in_sizes, int n_in,
                              void* d_out, int out_size) {
    // metadata order: pre_VF, pre_AF, back_VF, back_AF (only back_* are used)
    const float* VF = (const float*)d_in[2];
    const float* AF = (const float*)d_in[3];
    float* out = (float*)d_out;
    (void)in_sizes; (void)n_in; (void)out_size;

    stats_kernel<<<64, 256>>>(VF, AF);
    build_kernel<<<dim3(256, 2), 256>>>(VF, AF);
    main_kernel<<<dim3(TT / BN, TT / BM, BB), 256>>>(VF, AF, out);
}

// round 2
// speedup vs baseline: 1.6556x; 1.6556x over previous
#include <cuda_runtime.h>
#include <math.h>
#include <stddef.h>

// Problem constants (fixed by the reference: B=32, T=D=256)
#define BB 32
#define TT 256
#define DD 256
#define EPSF 1e-18f

// -------- scratch (device globals; no allocation allowed) --------
__device__ float g_part[2 * BB * 4 * TT]; // partial col sums of squares
__device__ float g_w1[BB * TT];   // rsqrt(colsum_t(back_AF[j,:,s]^2) + eps)
__device__ float g_w2[BB * TT];   // rsqrt(colsum_t(back_VF[j,:,s]^2) + eps)
__device__ float g_vi1[BB];       // rsqrt(frob2(back_VF_i) + eps)
__device__ float g_vi2[BB];       // rsqrt(frob2(back_AF_i) + eps)
__device__ float g_R1[TT * DD];   // R1[s,d] = sum_j w1[j,s]*AF[j,s,d]
__device__ float g_R2[TT * DD];   // R2[s,d] = sum_j w2[j,s]*VF[j,s,d]

// ============================================================
// Kernel 1a: partial per-column sums of squares
// grid = 256 (isA(2) x i(32) x chunk(4)), 256 threads (one per column s)
// ============================================================
__global__ void stats1_kernel(const float* __restrict__ VF,
                              const float* __restrict__ AF) {
    int chunk = blockIdx.x & 3;
    int i     = (blockIdx.x >> 2) & 31;
    int isA   = blockIdx.x >> 7;
    const float* X = isA ? AF : VF;
    int s = threadIdx.x;

    const float* base = X + ((size_t)i * TT + chunk * 64) * DD + s;
    float acc = 0.f;
#pragma unroll 8
    for (int t = 0; t < 64; ++t) {
        float v = base[(size_t)t * DD];
        acc += v * v;
    }
    g_part[((isA * BB + i) * 4 + chunk) * TT + s] = acc;
}

// ============================================================
// Kernel 1b: finalize column norms + Frobenius norms
// grid = 64 (isA x i), 256 threads
// ============================================================
__global__ void stats2_kernel() {
    int i   = blockIdx.x & 31;
    int isA = blockIdx.x >> 5;
    int s   = threadIdx.x;

    const float* p = &g_part[(size_t)((isA * BB + i) * 4) * TT + s];
    float acc = p[0] + p[TT] + p[2 * TT] + p[3 * TT];
    float w = rsqrtf(acc + EPSF);
    if (isA) g_w1[i * TT + s] = w;   // colnorm of AF -> direction 1
    else     g_w2[i * TT + s] = w;   // colnorm of VF -> direction 2

    __shared__ float sh[256];
    sh[s] = acc;
    __syncthreads();
    for (int off = 128; off > 0; off >>= 1) {
        if (s < off) sh[s] += sh[s + off];
        __syncthreads();
    }
    if (s == 0) {
        float vi = rsqrtf(sh[0] + EPSF);
        if (isA) g_vi2[i] = vi;      // frob of AF -> direction 2 anchor norm
        else     g_vi1[i] = vi;      // frob of VF -> direction 1 anchor norm
    }
}

// ============================================================
// Kernel 2: fold the j-sum into one matrix per direction
// grid = (256, 2), 256 threads (one per d)
// ============================================================
__global__ void build_kernel(const float* __restrict__ VF,
                             const float* __restrict__ AF) {
    int s   = blockIdx.x;
    int dir = blockIdx.y;                 // 0: R1 from AF/w1, 1: R2 from VF/w2
    int d   = threadIdx.x;
    const float* X = dir ? VF : AF;
    const float* w = dir ? g_w2 : g_w1;

    float acc = 0.f;
#pragma unroll
    for (int j = 0; j < BB; ++j)
        acc += w[j * TT + s] * X[((size_t)j * TT + s) * DD + d];

    if (dir) g_R2[s * DD + d] = acc;
    else     g_R1[s * DD + d] = acc;
}

// ============================================================
// Kernel 3: fused DUAL-GEMM + polynomial-log epilogue
//   Bd1[s,:] = R1[s,:] - w1[i,s]*A_i[s,:]   (built at smem-load time)
//   Bd2[s,:] = R2[s,:] - w2[i,s]*V_i[s,:]
//   acc1 = V_i @ Bd1^T,  acc2 = A_i @ Bd2^T
//   out[i,t,s] = -(2*ln32 + log1p(vi1*acc1/32) + log1p(vi2*acc2/32))
// BM=128, BN=64, BK=16, 256 threads, 8x4 per thread, 2 accumulator sets.
// ============================================================
#define BM 128
#define BN 64
#define BK 16
#define LDPA 132   // padded leading dim for 128-row tiles (mult of 4)
#define LDPB 68    // padded leading dim for 64-row tiles  (mult of 4)

__global__ void __launch_bounds__(256, 2)
main_kernel(const float* __restrict__ VF,
            const float* __restrict__ AF,
            float* __restrict__ out) {
    const int i  = blockIdx.z;
    const int t0 = blockIdx.y * BM;
    const int s0 = blockIdx.x * BN;

    __shared__ float sV[BK * LDPA];
    __shared__ float sA[BK * LDPA];
    __shared__ float sB1[BK * LDPB];
    __shared__ float sB2[BK * LDPB];

    const int tid = threadIdx.x;
    // A-tiles (128 rows x 16 k): each thread loads two float4
    const int ra = tid >> 1;
    const int ca = (tid & 1) * 8;
    // B-tiles (64 rows x 16 k): each thread loads one float4 per source
    const int rb = tid >> 2;
    const int cb = (tid & 3) * 4;

    const float* pV  = VF + ((size_t)(i * TT + t0 + ra)) * DD + ca;
    const float* pA  = AF + ((size_t)(i * TT + t0 + ra)) * DD + ca;
    const float* pR1 = g_R1 + (size_t)(s0 + rb) * DD + cb;
    const float* pR2 = g_R2 + (size_t)(s0 + rb) * DD + cb;
    const float* pAi = AF + ((size_t)(i * TT + s0 + rb)) * DD + cb;
    const float* pVi = VF + ((size_t)(i * TT + s0 + rb)) * DD + cb;
    const float w1r = g_w1[i * TT + s0 + rb];
    const float w2r = g_w2[i * TT + s0 + rb];

    const int ty = tid >> 4;   // 0..15 -> output rows ty*8 .. +7
    const int tx = tid & 15;   // 0..15 -> output cols tx*4 .. +3

    float acc1[8][4] = {};
    float acc2[8][4] = {};

    for (int k0 = 0; k0 < DD; k0 += BK) {
        float4 v0 = *(const float4*)(pV + k0);
        float4 v1 = *(const float4*)(pV + k0 + 4);
        float4 a0 = *(const float4*)(pA + k0);
        float4 a1 = *(const float4*)(pA + k0 + 4);
        float4 r1 = *(const float4*)(pR1 + k0);
        float4 ai = *(const float4*)(pAi + k0);
        float4 r2 = *(const float4*)(pR2 + k0);
        float4 vv = *(const float4*)(pVi + k0);

        sV[(ca + 0) * LDPA + ra] = v0.x; sV[(ca + 1) * LDPA + ra] = v0.y;
        sV[(ca + 2) * LDPA + ra] = v0.z; sV[(ca + 3) * LDPA + ra] = v0.w;
        sV[(ca + 4) * LDPA + ra] = v1.x; sV[(ca + 5) * LDPA + ra] = v1.y;
        sV[(ca + 6) * LDPA + ra] = v1.z; sV[(ca + 7) * LDPA + ra] = v1.w;

        sA[(ca + 0) * LDPA + ra] = a0.x; sA[(ca + 1) * LDPA + ra] = a0.y;
        sA[(ca + 2) * LDPA + ra] = a0.z; sA[(ca + 3) * LDPA + ra] = a0.w;
        sA[(ca + 4) * LDPA + ra] = a1.x; sA[(ca + 5) * LDPA + ra] = a1.y;
        sA[(ca + 6) * LDPA + ra] = a1.z; sA[(ca + 7) * LDPA + ra] = a1.w;

        sB1[(cb + 0) * LDPB + rb] = r1.x - w1r * ai.x;
        sB1[(cb + 1) * LDPB + rb] = r1.y - w1r * ai.y;
        sB1[(cb + 2) * LDPB + rb] = r1.z - w1r * ai.z;
        sB1[(cb + 3) * LDPB + rb] = r1.w - w1r * ai.w;

        sB2[(cb + 0) * LDPB + rb] = r2.x - w2r * vv.x;
        sB2[(cb + 1) * LDPB + rb] = r2.y - w2r * vv.y;
        sB2[(cb + 2) * LDPB + rb] = r2.z - w2r * vv.z;
        sB2[(cb + 3) * LDPB + rb] = r2.w - w2r * vv.w;
        __syncthreads();

#pragma unroll
        for (int kk = 0; kk < BK; ++kk) {
            float4 av0 = *(const float4*)&sV[kk * LDPA + ty * 8];
            float4 av1 = *(const float4*)&sV[kk * LDPA + ty * 8 + 4];
            float4 aa0 = *(const float4*)&sA[kk * LDPA + ty * 8];
            float4 aa1 = *(const float4*)&sA[kk * LDPA + ty * 8 + 4];
            float4 b1v = *(const float4*)&sB1[kk * LDPB + tx * 4];
            float4 b2v = *(const float4*)&sB2[kk * LDPB + tx * 4];

            float av[8] = {av0.x, av0.y, av0.z, av0.w, av1.x, av1.y, av1.z, av1.w};
            float aa[8] = {aa0.x, aa0.y, aa0.z, aa0.w, aa1.x, aa1.y, aa1.z, aa1.w};
            float b1a[4] = {b1v.x, b1v.y, b1v.z, b1v.w};
            float b2a[4] = {b2v.x, b2v.y, b2v.z, b2v.w};
#pragma unroll
            for (int m = 0; m < 8; ++m) {
#pragma unroll
                for (int n = 0; n < 4; ++n) {
                    acc1[m][n] += av[m] * b1a[n];
                    acc2[m][n] += aa[m] * b2a[n];
                }
            }
        }
        __syncthreads();
    }

    // ---- epilogue: -(log(32+e1) + log(32+e2)) with polynomial log1p ----
    const float vi1 = g_vi1[i];
    const float vi2 = g_vi2[i];
    const float INV32 = 1.0f / 32.0f;
    const float TWO_LN32 = 6.931471805599453f;  // 2*ln(32)

#pragma unroll
    for (int m = 0; m < 8; ++m) {
        const int t = t0 + ty * 8 + m;
        float res[4];
#pragma unroll
        for (int n = 0; n < 4; ++n) {
            float x1 = vi1 * acc1[m][n] * INV32;
            float x2 = vi2 * acc2[m][n] * INV32;
            float p1, p2;
            if (fabsf(x1) < 0.0625f) {
                p1 = x1 * fmaf(x1, fmaf(x1, fmaf(x1, -0.25f, 0.33333333333f), -0.5f), 1.0f);
            } else {
                p1 = log1pf(x1);
            }
            if (fabsf(x2) < 0.0625f) {
                p2 = x2 * fmaf(x2, fmaf(x2, fmaf(x2, -0.25f, 0.33333333333f), -0.5f), 1.0f);
            } else {
                p2 = log1pf(x2);
            }
            res[n] = -(TWO_LN32 + p1 + p2);
        }
        float4 o = {res[0], res[1], res[2], res[3]};
        *(float4*)&out[((size_t)(i * TT + t)) * TT + s0 + tx * 4] = o;
    }
}

// ============================================================
extern "C" void kernel_launch(void* const* d_in, const int* in_sizes, int n_in,
                              void* d_out, int out_size) {
    // metadata order: pre_VF, pre_AF, back_VF, back_AF (only back_* are used)
    const float* VF = (const float*)d_in[2];
    const float* AF = (const float*)d_in[3];
    float* out = (float*)d_out;
    (void)in_sizes; (void)n_in; (void)out_size;

    stats1_kernel<<<256, 256>>>(VF, AF);
    stats2_kernel<<<64, 256>>>();
    build_kernel<<<dim3(256, 2), 256>>>(VF, AF);
    main_kernel<<<dim3(TT / BN, TT / BM, BB), 256>>>(VF, AF, out);
}

// round 4
// speedup vs baseline: 3.7756x; 2.2805x over previous
#include <cuda_runtime.h>
#include <cuda_bf16.h>
#include <stdint.h>
#include <math.h>
#include <stddef.h>

// Problem constants (fixed by the reference: B=32, T=D=256)
#define BB 32
#define TT 256
#define DD 256
#define EPSF 1e-18f

// -------- scratch (device globals; no allocation allowed) --------
__device__ float g_part[2 * BB * 4 * TT];
__device__ float g_w1[BB * TT];   // rsqrt(colsum_t(back_AF[j,:,s]^2) + eps)
__device__ float g_w2[BB * TT];   // rsqrt(colsum_t(back_VF[j,:,s]^2) + eps)
__device__ float g_vi1[BB];       // rsqrt(frob2(back_VF_i) + eps)
__device__ float g_vi2[BB];       // rsqrt(frob2(back_AF_i) + eps)
// bf16 payloads stored as POD unsigned short (bit-identical to __nv_bfloat16)
__device__ __align__(16) unsigned short g_VFb[BB * TT * DD];
__device__ __align__(16) unsigned short g_AFb[BB * TT * DD];
__device__ __align__(16) unsigned short g_R1b[TT * DD]; // R1[s,d]=sum_j w1[j,s]*AF[j,s,d]
__device__ __align__(16) unsigned short g_R2b[TT * DD]; // R2[s,d]=sum_j w2[j,s]*VF[j,s,d]

__device__ __forceinline__ uint32_t smem_u32(const void* p) {
    uint32_t r;
    asm("{ .reg .u64 t; cvta.to.shared.u64 t, %1; cvt.u32.u64 %0, t; }"
        : "=r"(r) : "l"(p));
    return r;
}

// ============================================================
// Kernel 1a: partial col sums of squares (fp32, exact) + bf16 convert
// grid = 256 (isA(2) x i(32) x chunk(4)), 256 threads (one per column s)
// ============================================================
__global__ void stats1_kernel(const float* __restrict__ VF,
                              const float* __restrict__ AF) {
    int chunk = blockIdx.x & 3;
    int i     = (blockIdx.x >> 2) & 31;
    int isA   = blockIdx.x >> 7;
    const float* X = isA ? AF : VF;
    unsigned short* Xb = isA ? g_AFb : g_VFb;
    int s = threadIdx.x;

    size_t base = ((size_t)i * TT + chunk * 64) * DD + s;
    float acc = 0.f;
#pragma unroll 4
    for (int t = 0; t < 64; ++t) {
        float v = X[base + (size_t)t * DD];
        acc += v * v;
        Xb[base + (size_t)t * DD] = __bfloat16_as_ushort(__float2bfloat16(v));
    }
    g_part[((isA * BB + i) * 4 + chunk) * TT + s] = acc;
}

// ============================================================
// Kernel 1b: finalize column norms + Frobenius norms
// ============================================================
__global__ void stats2_kernel() {
    int i   = blockIdx.x & 31;
    int isA = blockIdx.x >> 5;
    int s   = threadIdx.x;

    const float* p = &g_part[(size_t)((isA * BB + i) * 4) * TT + s];
    float acc = p[0] + p[TT] + p[2 * TT] + p[3 * TT];
    float w = rsqrtf(acc + EPSF);
    if (isA) g_w1[i * TT + s] = w;
    else     g_w2[i * TT + s] = w;

    __shared__ float sh[256];
    sh[s] = acc;
    __syncthreads();
    for (int off = 128; off > 0; off >>= 1) {
        if (s < off) sh[s] += sh[s + off];
        __syncthreads();
    }
    if (s == 0) {
        float vi = rsqrtf(sh[0] + EPSF);
        if (isA) g_vi2[i] = vi;
        else     g_vi1[i] = vi;
    }
}

// ============================================================
// Kernel 2: fold the j-sum, output bf16
// ============================================================
__global__ void build_kernel() {
    int s   = blockIdx.x;
    int dir = blockIdx.y;                 // 0: R1 from AFb/w1, 1: R2 from VFb/w2
    int d   = threadIdx.x;
    const unsigned short* X = dir ? g_VFb : g_AFb;
    const float* w = dir ? g_w2 : g_w1;

    float acc = 0.f;
#pragma unroll
    for (int j = 0; j < BB; ++j)
        acc += w[j * TT + s] *
               __bfloat162float(__ushort_as_bfloat16(X[((size_t)j * TT + s) * DD + d]));

    unsigned short r = __bfloat16_as_ushort(__float2bfloat16(acc));
    if (dir) g_R2b[s * DD + d] = r;
    else     g_R1b[s * DD + d] = r;
}

// ============================================================
// Kernel 3: tensor-core dual-GEMM (bf16 HMMA) + polynomial-log epilogue
//   Bd1[s,:] = R1[s,:] - w1[i,s]*A_i[s,:]   (folded at smem-store time)
//   Bd2[s,:] = R2[s,:] - w2[i,s]*V_i[s,:]
//   acc1 = V_i @ Bd1^T, acc2 = A_i @ Bd2^T   (fp32 accumulate)
//   out = -(2*ln32 + log1p(vi1*acc1/32) + log1p(vi2*acc2/32))
// BM=BN=128, BK=32, 256 threads (8 warps 4x2), warp tile 32x64 per GEMM.
// grid = 2 x 2 x 32 = 128 CTAs -> single wave.
// ============================================================
#define LDE 40   // smem row stride in bf16 elems (80B: 16B-aligned, ldmatrix conflict-free)

__device__ __forceinline__ void ldsm4(uint32_t* r, uint32_t addr) {
    asm volatile("ldmatrix.sync.aligned.m8n8.x4.shared.b16 {%0,%1,%2,%3}, [%4];"
                 : "=r"(r[0]), "=r"(r[1]), "=r"(r[2]), "=r"(r[3]) : "r"(addr));
}

__device__ __forceinline__ void mma_bf16(float* c, const uint32_t* a, const uint32_t* b) {
    asm volatile("mma.sync.aligned.m16n8k16.row.col.f32.bf16.bf16.f32 "
                 "{%0,%1,%2,%3},{%4,%5,%6,%7},{%8,%9},{%0,%1,%2,%3};"
                 : "+f"(c[0]), "+f"(c[1]), "+f"(c[2]), "+f"(c[3])
                 : "r"(a[0]), "r"(a[1]), "r"(a[2]), "r"(a[3]),
                   "r"(b[0]), "r"(b[1]));
}

__device__ __forceinline__ uint32_t fold2(uint32_t r, uint32_t a, float w) {
    __nv_bfloat162 rb, ab;
    rb = *(const __nv_bfloat162*)&r;
    ab = *(const __nv_bfloat162*)&a;
    float2 rf = __bfloat1622float2(rb);
    float2 af = __bfloat1622float2(ab);
    float2 d;
    d.x = rf.x - w * af.x;
    d.y = rf.y - w * af.y;
    __nv_bfloat162 db = __float22bfloat162_rn(d);
    return *(uint32_t*)&db;
}

__device__ __forceinline__ uint4 fold4(uint4 r, uint4 a, float w) {
    uint4 o;
    o.x = fold2(r.x, a.x, w); o.y = fold2(r.y, a.y, w);
    o.z = fold2(r.z, a.z, w); o.w = fold2(r.w, a.w, w);
    return o;
}

__device__ __forceinline__ float lg1p(float x) {
    if (fabsf(x) < 0.0625f)
        return x * fmaf(x, fmaf(x, fmaf(x, -0.25f, 0.33333333333f), -0.5f), 1.0f);
    return log1pf(x);
}

__global__ void __launch_bounds__(256, 1)
main_kernel(float* __restrict__ out) {
    const int i  = blockIdx.z;
    const int t0 = blockIdx.y * 128;
    const int s0 = blockIdx.x * 128;

    __shared__ __align__(16) unsigned short sV[128 * LDE];
    __shared__ __align__(16) unsigned short sA[128 * LDE];
    __shared__ __align__(16) unsigned short sB1[128 * LDE];
    __shared__ __align__(16) unsigned short sB2[128 * LDE];

    const int tid  = threadIdx.x;
    const int lane = tid & 31;
    const int wid  = tid >> 5;
    const int wm   = wid >> 1;   // 0..3
    const int wn   = wid & 1;    // 0..1

    // global->smem load mapping: each thread loads 2 rows x 8 elems per tile
    const int row0 = tid >> 2;          // 0..63
    const int col8 = (tid & 3) * 8;     // 0,8,16,24
    const size_t R64 = (size_t)64 * DD;

    const unsigned short* pV  = g_VFb + ((size_t)(i * TT + t0 + row0)) * DD + col8;
    const unsigned short* pA  = g_AFb + ((size_t)(i * TT + t0 + row0)) * DD + col8;
    const unsigned short* pR1 = g_R1b + ((size_t)(s0 + row0)) * DD + col8;
    const unsigned short* pR2 = g_R2b + ((size_t)(s0 + row0)) * DD + col8;
    const unsigned short* pAi = g_AFb + ((size_t)(i * TT + s0 + row0)) * DD + col8;
    const unsigned short* pVi = g_VFb + ((size_t)(i * TT + s0 + row0)) * DD + col8;

    const float w1a = g_w1[i * TT + s0 + row0];
    const float w1b = g_w1[i * TT + s0 + row0 + 64];
    const float w2a = g_w2[i * TT + s0 + row0];
    const float w2b = g_w2[i * TT + s0 + row0 + 64];

    float acc1[2][8][4] = {};
    float acc2[2][8][4] = {};

    // ldmatrix base byte-addresses (per thread)
    const uint32_t sVu  = smem_u32(sV);
    const uint32_t sAu  = smem_u32(sA);
    const uint32_t sB1u = smem_u32(sB1);
    const uint32_t sB2u = smem_u32(sB2);
    const uint32_t arel = (uint32_t)(((wm * 32 + (lane & 15)) * LDE + ((lane >> 4) * 8)) * 2);
    const uint32_t brel = (uint32_t)(((wn * 64 + (lane & 7) + ((lane & 16) >> 1)) * LDE
                                      + (((lane >> 3) & 1) * 8)) * 2);

    // prologue: load tile 0 into registers
    uint4 rv0  = *(const uint4*)(pV);    uint4 rv1  = *(const uint4*)(pV + R64);
    uint4 ra0  = *(const uint4*)(pA);    uint4 ra1  = *(const uint4*)(pA + R64);
    uint4 rr10 = *(const uint4*)(pR1);   uint4 rr11 = *(const uint4*)(pR1 + R64);
    uint4 rai0 = *(const uint4*)(pAi);   uint4 rai1 = *(const uint4*)(pAi + R64);
    uint4 rr20 = *(const uint4*)(pR2);   uint4 rr21 = *(const uint4*)(pR2 + R64);
    uint4 rvi0 = *(const uint4*)(pVi);   uint4 rvi1 = *(const uint4*)(pVi + R64);

    const int so0 = row0 * LDE + col8;
    const int so1 = (row0 + 64) * LDE + col8;

    for (int k0 = 0; k0 < 8; ++k0) {
        if (k0) __syncthreads();   // mma of previous tile done reading smem
        *(uint4*)&sV[so0] = rv0;   *(uint4*)&sV[so1] = rv1;
        *(uint4*)&sA[so0] = ra0;   *(uint4*)&sA[so1] = ra1;
        *(uint4*)&sB1[so0] = fold4(rr10, rai0, w1a);
        *(uint4*)&sB1[so1] = fold4(rr11, rai1, w1b);
        *(uint4*)&sB2[so0] = fold4(rr20, rvi0, w2a);
        *(uint4*)&sB2[so1] = fold4(rr21, rvi1, w2b);
        __syncthreads();

        if (k0 < 7) {  // prefetch next tile into regs (hidden under mma)
            const int ko = (k0 + 1) * 32;
            rv0  = *(const uint4*)(pV + ko);   rv1  = *(const uint4*)(pV + R64 + ko);
            ra0  = *(const uint4*)(pA + ko);   ra1  = *(const uint4*)(pA + R64 + ko);
            rr10 = *(const uint4*)(pR1 + ko);  rr11 = *(const uint4*)(pR1 + R64 + ko);
            rai0 = *(const uint4*)(pAi + ko);  rai1 = *(const uint4*)(pAi + R64 + ko);
            rr20 = *(const uint4*)(pR2 + ko);  rr21 = *(const uint4*)(pR2 + R64 + ko);
            rvi0 = *(const uint4*)(pVi + ko);  rvi1 = *(const uint4*)(pVi + R64 + ko);
        }

#pragma unroll
        for (int ks = 0; ks < 2; ++ks) {
            uint32_t av[2][4];
            uint32_t aa[2][4];
#pragma unroll
            for (int mf = 0; mf < 2; ++mf) {
                const uint32_t ao = (uint32_t)((mf * 16 * LDE + ks * 16) * 2);
                ldsm4(av[mf], sVu + arel + ao);
                ldsm4(aa[mf], sAu + arel + ao);
            }
#pragma unroll
            for (int nb = 0; nb < 4; ++nb) {
                const uint32_t bo = (uint32_t)((nb * 16 * LDE + ks * 16) * 2);
                uint32_t b1[4];
                uint32_t b2[4];
                ldsm4(b1, sB1u + brel + bo);
                ldsm4(b2, sB2u + brel + bo);
#pragma unroll
                for (int mf = 0; mf < 2; ++mf) {
                    mma_bf16(acc1[mf][nb * 2],     av[mf], &b1[0]);
                    mma_bf16(acc1[mf][nb * 2 + 1], av[mf], &b1[2]);
                    mma_bf16(acc2[mf][nb * 2],     aa[mf], &b2[0]);
                    mma_bf16(acc2[mf][nb * 2 + 1], aa[mf], &b2[2]);
                }
            }
        }
    }

    // ---- epilogue ----
    const float vi1 = g_vi1[i];
    const float vi2 = g_vi2[i];
    const float INV32 = 1.0f / 32.0f;
    const float TWO_LN32 = 6.931471805599453f;

#pragma unroll
    for (int mf = 0; mf < 2; ++mf) {
        const int rbase = t0 + wm * 32 + mf * 16 + (lane >> 2);
#pragma unroll
        for (int n8 = 0; n8 < 8; ++n8) {
            const int col = s0 + wn * 64 + n8 * 8 + (lane & 3) * 2;
            const float* c1 = acc1[mf][n8];
            const float* c2 = acc2[mf][n8];
            float2 o0, o1;
            o0.x = -(TWO_LN32 + lg1p(vi1 * c1[0] * INV32) + lg1p(vi2 * c2[0] * INV32));
            o0.y = -(TWO_LN32 + lg1p(vi1 * c1[1] * INV32) + lg1p(vi2 * c2[1] * INV32));
            o1.x = -(TWO_LN32 + lg1p(vi1 * c1[2] * INV32) + lg1p(vi2 * c2[2] * INV32));
            o1.y = -(TWO_LN32 + lg1p(vi1 * c1[3] * INV32) + lg1p(vi2 * c2[3] * INV32));
            *(float2*)&out[((size_t)(i * TT + rbase)) * TT + col] = o0;
            *(float2*)&out[((size_t)(i * TT + rbase + 8)) * TT + col] = o1;
        }
    }
}

// ============================================================
extern "C" void kernel_launch(void* const* d_in, const int* in_sizes, int n_in,
                              void* d_out, int out_size) {
    // metadata order: pre_VF, pre_AF, back_VF, back_AF (only back_* are used)
    const float* VF = (const float*)d_in[2];
    const float* AF = (const float*)d_in[3];
    float* out = (float*)d_out;
    (void)in_sizes; (void)n_in; (void)out_size;

    stats1_kernel<<<256, 256>>>(VF, AF);
    stats2_kernel<<<64, 256>>>();
    build_kernel<<<dim3(256, 2), 256>>>();
    main_kernel<<<dim3(2, 2, 32), 256>>>(out);
}

// round 5
// speedup vs baseline: 4.2442x; 1.1241x over previous
#include <cuda_runtime.h>
#include <cuda_bf16.h>
#include <stdint.h>
#include <math.h>
#include <stddef.h>

// Problem constants (fixed by the reference: B=32, T=D=256)
#define BB 32
#define TT 256
#define DD 256
#define EPSF 1e-18f

// -------- scratch (device globals; no allocation allowed) --------
__device__ float g_part[2 * BB * 4 * TT];
__device__ float g_w1[BB * TT];   // rsqrt(colsum_t(back_AF[j,:,s]^2) + eps)
__device__ float g_w2[BB * TT];   // rsqrt(colsum_t(back_VF[j,:,s]^2) + eps)
__device__ float g_vi1[BB];       // rsqrt(frob2(back_VF_i) + eps)
__device__ float g_vi2[BB];       // rsqrt(frob2(back_AF_i) + eps)
// bf16 payloads stored as POD unsigned short
__device__ __align__(16) unsigned short g_VFb[BB * TT * DD];
__device__ __align__(16) unsigned short g_AFb[BB * TT * DD];
// Folded B operands: Bd1[i,s,d] = R1[s,d]-w1[i,s]*AF[i,s,d], Bd2 likewise with V
__device__ __align__(16) unsigned short g_Bd1[BB * TT * DD];
__device__ __align__(16) unsigned short g_Bd2[BB * TT * DD];

__device__ __forceinline__ uint32_t smem_u32(const void* p) {
    uint32_t r;
    asm("{ .reg .u64 t; cvta.to.shared.u64 t, %1; cvt.u32.u64 %0, t; }"
        : "=r"(r) : "l"(p));
    return r;
}

// ============================================================
// Kernel 1a: partial col sums of squares (fp32, exact) + bf16 convert
// ============================================================
__global__ void stats1_kernel(const float* __restrict__ VF,
                              const float* __restrict__ AF) {
    int chunk = blockIdx.x & 3;
    int i     = (blockIdx.x >> 2) & 31;
    int isA   = blockIdx.x >> 7;
    const float* X = isA ? AF : VF;
    unsigned short* Xb = isA ? g_AFb : g_VFb;
    int s = threadIdx.x;

    size_t base = ((size_t)i * TT + chunk * 64) * DD + s;
    float acc = 0.f;
#pragma unroll 4
    for (int t = 0; t < 64; ++t) {
        float v = X[base + (size_t)t * DD];
        acc += v * v;
        Xb[base + (size_t)t * DD] = __bfloat16_as_ushort(__float2bfloat16(v));
    }
    g_part[((isA * BB + i) * 4 + chunk) * TT + s] = acc;
}

// ============================================================
// Kernel 1b: finalize column norms + Frobenius norms
// ============================================================
__global__ void stats2_kernel() {
    int i   = blockIdx.x & 31;
    int isA = blockIdx.x >> 5;
    int s   = threadIdx.x;

    const float* p = &g_part[(size_t)((isA * BB + i) * 4) * TT + s];
    float acc = p[0] + p[TT] + p[2 * TT] + p[3 * TT];
    float w = rsqrtf(acc + EPSF);
    if (isA) g_w1[i * TT + s] = w;
    else     g_w2[i * TT + s] = w;

    __shared__ float sh[256];
    sh[s] = acc;
    __syncthreads();
    for (int off = 128; off > 0; off >>= 1) {
        if (s < off) sh[s] += sh[s + off];
        __syncthreads();
    }
    if (s == 0) {
        float vi = rsqrtf(sh[0] + EPSF);
        if (isA) g_vi2[i] = vi;
        else     g_vi1[i] = vi;
    }
}

// ============================================================
// Kernel 2: fold j-sum AND per-i correction into Bd matrices.
//   R[s,d]     = sum_j w[j,s]*X[j,s,d]
//   Bd[i,s,d]  = R[s,d] - w[i,s]*X[i,s,d]
// grid (256 s, 2 dir), 256 threads (d). X values reused from registers.
// ============================================================
__global__ void build_kernel() {
    int s   = blockIdx.x;
    int dir = blockIdx.y;                 // 0: from AFb/w1 -> Bd1, 1: from VFb/w2 -> Bd2
    int d   = threadIdx.x;
    const unsigned short* X = dir ? g_VFb : g_AFb;
    const float* w = dir ? g_w2 : g_w1;
    unsigned short* Bd = dir ? g_Bd2 : g_Bd1;

    __shared__ float sw[BB];
    if (d < BB) sw[d] = w[d * TT + s];
    __syncthreads();

    float xv[BB];
    float R = 0.f;
#pragma unroll
    for (int j = 0; j < BB; ++j) {
        xv[j] = __bfloat162float(__ushort_as_bfloat16(X[((size_t)j * TT + s) * DD + d]));
        R += sw[j] * xv[j];
    }
#pragma unroll
    for (int j = 0; j < BB; ++j) {
        float v = R - sw[j] * xv[j];
        Bd[((size_t)j * TT + s) * DD + d] = __bfloat16_as_ushort(__float2bfloat16(v));
    }
}

// ============================================================
// Kernel 3: cp.async-pipelined tensor-core dual-GEMM + poly-log epilogue
//   acc1 = V_i @ Bd1_i^T, acc2 = A_i @ Bd2_i^T  (bf16 HMMA, fp32 accum)
//   out = -(2*ln32 + log1p(vi1*acc1/32) + log1p(vi2*acc2/32))
// BM=BN=128, BK=32, 256 threads (8 warps 4x2), warp tile 32x64 per GEMM.
// 3-stage cp.async pipeline, one __syncthreads per k-tile.
// grid = 2 x 2 x 32 = 128 CTAs -> single wave.
// ============================================================
#define LDE 40                    // smem row stride in bf16 elems (80B)
#define TILE_ELE (128 * LDE)      // 5120 elems = 10240 B per tile
#define STAGE_BYTES (4 * TILE_ELE * 2)  // 40960 B per stage (V,A,B1,B2)
#define STAGES 3
#define SMEM_BYTES (STAGES * STAGE_BYTES)  // 122880

__device__ __forceinline__ void ldsm4(uint32_t* r, uint32_t addr) {
    asm volatile("ldmatrix.sync.aligned.m8n8.x4.shared.b16 {%0,%1,%2,%3}, [%4];"
                 : "=r"(r[0]), "=r"(r[1]), "=r"(r[2]), "=r"(r[3]) : "r"(addr));
}

__device__ __forceinline__ void mma_bf16(float* c, const uint32_t* a, const uint32_t* b) {
    asm volatile("mma.sync.aligned.m16n8k16.row.col.f32.bf16.bf16.f32 "
                 "{%0,%1,%2,%3},{%4,%5,%6,%7},{%8,%9},{%0,%1,%2,%3};"
                 : "+f"(c[0]), "+f"(c[1]), "+f"(c[2]), "+f"(c[3])
                 : "r"(a[0]), "r"(a[1]), "r"(a[2]), "r"(a[3]),
                   "r"(b[0]), "r"(b[1]));
}

__device__ __forceinline__ void cpa16(uint32_t dst, const void* src) {
    asm volatile("cp.async.cg.shared.global [%0], [%1], 16;\n"
                 :: "r"(dst), "l"(src) : "memory");
}

__device__ __forceinline__ float lg1p(float x) {
    if (fabsf(x) < 0.0625f)
        return x * fmaf(x, fmaf(x, fmaf(x, -0.25f, 0.33333333333f), -0.5f), 1.0f);
    return log1pf(x);
}

__global__ void __launch_bounds__(256, 1)
main_kernel(float* __restrict__ out) {
    extern __shared__ unsigned short dynsmem[];
    const uint32_t sbase = smem_u32(dynsmem);

    const int i  = blockIdx.z;
    const int t0 = blockIdx.y * 128;
    const int s0 = blockIdx.x * 128;

    const int tid  = threadIdx.x;
    const int lane = tid & 31;
    const int wid  = tid >> 5;
    const int wm   = wid >> 1;   // 0..3
    const int wn   = wid & 1;    // 0..1

    // global->smem mapping: each thread loads 2 rows x 8 elems per tile
    const int row0 = tid >> 2;          // 0..63
    const int col8 = (tid & 3) * 8;     // 0,8,16,24
    const size_t R64 = (size_t)64 * DD;

    const unsigned short* pV  = g_VFb + ((size_t)(i * TT + t0 + row0)) * DD + col8;
    const unsigned short* pA  = g_AFb + ((size_t)(i * TT + t0 + row0)) * DD + col8;
    const unsigned short* pB1 = g_Bd1 + ((size_t)(i * TT + s0 + row0)) * DD + col8;
    const unsigned short* pB2 = g_Bd2 + ((size_t)(i * TT + s0 + row0)) * DD + col8;

    const uint32_t so0b = (uint32_t)((row0 * LDE + col8) * 2);
    const uint32_t so1b = (uint32_t)(((row0 + 64) * LDE + col8) * 2);

    float acc1[2][8][4] = {};
    float acc2[2][8][4] = {};

    // ldmatrix per-thread relative byte offsets (within a tile)
    const uint32_t arel = (uint32_t)(((wm * 32 + (lane & 15)) * LDE + ((lane >> 4) * 8)) * 2);
    const uint32_t brel = (uint32_t)(((wn * 64 + (lane & 7) + ((lane & 16) >> 1)) * LDE
                                      + (((lane >> 3) & 1) * 8)) * 2);

    // ---- issue one stage's 8 cp.asyncs + commit ----
#define ISSUE_STAGE(buf, k)                                                    \
    do {                                                                       \
        const uint32_t b_ = sbase + (uint32_t)(buf) * STAGE_BYTES;             \
        const int ko_ = (k) * 32;                                              \
        cpa16(b_ + 0 * (TILE_ELE * 2) + so0b, pV + ko_);                       \
        cpa16(b_ + 0 * (TILE_ELE * 2) + so1b, pV + R64 + ko_);                 \
        cpa16(b_ + 1 * (TILE_ELE * 2) + so0b, pA + ko_);                       \
        cpa16(b_ + 1 * (TILE_ELE * 2) + so1b, pA + R64 + ko_);                 \
        cpa16(b_ + 2 * (TILE_ELE * 2) + so0b, pB1 + ko_);                      \
        cpa16(b_ + 2 * (TILE_ELE * 2) + so1b, pB1 + R64 + ko_);                \
        cpa16(b_ + 3 * (TILE_ELE * 2) + so0b, pB2 + ko_);                      \
        cpa16(b_ + 3 * (TILE_ELE * 2) + so1b, pB2 + R64 + ko_);                \
        asm volatile("cp.async.commit_group;\n" ::: "memory");                 \
    } while (0)

    // prologue: fill stages 0,1
    ISSUE_STAGE(0, 0);
    ISSUE_STAGE(1, 1);

#pragma unroll
    for (int k0 = 0; k0 < 8; ++k0) {
        // group k0 must be complete; every iteration commits exactly one group
        asm volatile("cp.async.wait_group 1;\n" ::: "memory");
        __syncthreads();   // also: all warps done with buffer (k0-1)%STAGES

        if (k0 + 2 < 8) {
            ISSUE_STAGE((k0 + 2) % STAGES, k0 + 2);
        } else {
            asm volatile("cp.async.commit_group;\n" ::: "memory");  // empty group
        }

        const uint32_t bV  = sbase + (uint32_t)((k0 % STAGES)) * STAGE_BYTES;
        const uint32_t bA  = bV + 1 * (TILE_ELE * 2);
        const uint32_t bB1 = bV + 2 * (TILE_ELE * 2);
        const uint32_t bB2 = bV + 3 * (TILE_ELE * 2);

#pragma unroll
        for (int ks = 0; ks < 2; ++ks) {
            uint32_t av[2][4];
            uint32_t aa[2][4];
#pragma unroll
            for (int mf = 0; mf < 2; ++mf) {
                const uint32_t ao = (uint32_t)((mf * 16 * LDE + ks * 16) * 2);
                ldsm4(av[mf], bV + arel + ao);
                ldsm4(aa[mf], bA + arel + ao);
            }
#pragma unroll
            for (int nb = 0; nb < 4; ++nb) {
                const uint32_t bo = (uint32_t)((nb * 16 * LDE + ks * 16) * 2);
                uint32_t b1[4];
                uint32_t b2[4];
                ldsm4(b1, bB1 + brel + bo);
                ldsm4(b2, bB2 + brel + bo);
#pragma unroll
                for (int mf = 0; mf < 2; ++mf) {
                    mma_bf16(acc1[mf][nb * 2],     av[mf], &b1[0]);
                    mma_bf16(acc1[mf][nb * 2 + 1], av[mf], &b1[2]);
                    mma_bf16(acc2[mf][nb * 2],     aa[mf], &b2[0]);
                    mma_bf16(acc2[mf][nb * 2 + 1], aa[mf], &b2[2]);
                }
            }
        }
    }

    // ---- epilogue ----
    const float vi1 = g_vi1[i];
    const float vi2 = g_vi2[i];
    const float INV32 = 1.0f / 32.0f;
    const float TWO_LN32 = 6.931471805599453f;

#pragma unroll
    for (int mf = 0; mf < 2; ++mf) {
        const int rbase = t0 + wm * 32 + mf * 16 + (lane >> 2);
#pragma unroll
        for (int n8 = 0; n8 < 8; ++n8) {
            const int col = s0 + wn * 64 + n8 * 8 + (lane & 3) * 2;
            const float* c1 = acc1[mf][n8];
            const float* c2 = acc2[mf][n8];
            float2 o0, o1;
            o0.x = -(TWO_LN32 + lg1p(vi1 * c1[0] * INV32) + lg1p(vi2 * c2[0] * INV32));
            o0.y = -(TWO_LN32 + lg1p(vi1 * c1[1] * INV32) + lg1p(vi2 * c2[1] * INV32));
            o1.x = -(TWO_LN32 + lg1p(vi1 * c1[2] * INV32) + lg1p(vi2 * c2[2] * INV32));
            o1.y = -(TWO_LN32 + lg1p(vi1 * c1[3] * INV32) + lg1p(vi2 * c2[3] * INV32));
            *(float2*)&out[((size_t)(i * TT + rbase)) * TT + col] = o0;
            *(float2*)&out[((size_t)(i * TT + rbase + 8)) * TT + col] = o1;
        }
    }
}

// ============================================================
extern "C" void kernel_launch(void* const* d_in, const int* in_sizes, int n_in,
                              void* d_out, int out_size) {
    // metadata order: pre_VF, pre_AF, back_VF, back_AF (only back_* are used)
    const float* VF = (const float*)d_in[2];
    const float* AF = (const float*)d_in[3];
    float* out = (float*)d_out;
    (void)in_sizes; (void)n_in; (void)out_size;

    cudaFuncSetAttribute(main_kernel,
                         cudaFuncAttributeMaxDynamicSharedMemorySize, SMEM_BYTES);

    stats1_kernel<<<256, 256>>>(VF, AF);
    stats2_kernel<<<64, 256>>>();
    build_kernel<<<dim3(256, 2), 256>>>();
    main_kernel<<<dim3(2, 2, 32), 256, SMEM_BYTES>>>(out);
}

// round 7
// speedup vs baseline: 4.9198x; 1.1592x over previous
#include <cuda_runtime.h>
#include <cuda_bf16.h>
#include <stdint.h>
#include <math.h>
#include <stddef.h>

// Problem constants (fixed by the reference: B=32, T=D=256)
#define BB 32
#define TT 256
#define DD 256
#define EPSF 1e-18f

// -------- scratch (device globals; no allocation allowed) --------
__device__ float g_part[2 * BB * 4 * TT];
__device__ float g_w1[BB * TT];
__device__ float g_w2[BB * TT];
__device__ float g_vi1[BB];
__device__ float g_vi2[BB];
__device__ __align__(16) unsigned short g_VFb[BB * TT * DD];
__device__ __align__(16) unsigned short g_AFb[BB * TT * DD];
// Folded B operands: Bd1[i,s,d] = R1[s,d]-w1[i,s]*AF[i,s,d], Bd2 likewise with V
__device__ __align__(16) unsigned short g_Bd1[BB * TT * DD];
__device__ __align__(16) unsigned short g_Bd2[BB * TT * DD];

__device__ __forceinline__ uint32_t smem_u32(const void* p) {
    uint32_t r;
    asm("{ .reg .u64 t; cvta.to.shared.u64 t, %1; cvt.u32.u64 %0, t; }"
        : "=r"(r) : "l"(p));
    return r;
}

// ============================================================
// Kernel 1a: partial col sums of squares (fp32, exact) + bf16 convert
// ============================================================
__global__ void stats1_kernel(const float* __restrict__ VF,
                              const float* __restrict__ AF) {
    int chunk = blockIdx.x & 3;
    int i     = (blockIdx.x >> 2) & 31;
    int isA   = blockIdx.x >> 7;
    const float* X = isA ? AF : VF;
    unsigned short* Xb = isA ? g_AFb : g_VFb;
    int s = threadIdx.x;

    size_t base = ((size_t)i * TT + chunk * 64) * DD + s;
    float acc = 0.f;
#pragma unroll 4
    for (int t = 0; t < 64; ++t) {
        float v = X[base + (size_t)t * DD];
        acc += v * v;
        Xb[base + (size_t)t * DD] = __bfloat16_as_ushort(__float2bfloat16(v));
    }
    g_part[((isA * BB + i) * 4 + chunk) * TT + s] = acc;
}

// ============================================================
// Kernel 1b: finalize column norms + Frobenius norms
// ============================================================
__global__ void stats2_kernel() {
    int i   = blockIdx.x & 31;
    int isA = blockIdx.x >> 5;
    int s   = threadIdx.x;

    const float* p = &g_part[(size_t)((isA * BB + i) * 4) * TT + s];
    float acc = p[0] + p[TT] + p[2 * TT] + p[3 * TT];
    float w = rsqrtf(acc + EPSF);
    if (isA) g_w1[i * TT + s] = w;
    else     g_w2[i * TT + s] = w;

    __shared__ float sh[256];
    sh[s] = acc;
    __syncthreads();
    for (int off = 128; off > 0; off >>= 1) {
        if (s < off) sh[s] += sh[s + off];
        __syncthreads();
    }
    if (s == 0) {
        float vi = rsqrtf(sh[0] + EPSF);
        if (isA) g_vi2[i] = vi;
        else     g_vi1[i] = vi;
    }
}

// ============================================================
// Kernel 2: fold j-sum AND per-i correction into Bd matrices.
// ============================================================
__global__ void build_kernel() {
    int s   = blockIdx.x;
    int dir = blockIdx.y;
    int d   = threadIdx.x;
    const unsigned short* X = dir ? g_VFb : g_AFb;
    const float* w = dir ? g_w2 : g_w1;
    unsigned short* Bd = dir ? g_Bd2 : g_Bd1;

    __shared__ float sw[BB];
    if (d < BB) sw[d] = w[d * TT + s];
    __syncthreads();

    float xv[BB];
    float R = 0.f;
#pragma unroll
    for (int j = 0; j < BB; ++j) {
        xv[j] = __bfloat162float(__ushort_as_bfloat16(X[((size_t)j * TT + s) * DD + d]));
        R += sw[j] * xv[j];
    }
#pragma unroll
    for (int j = 0; j < BB; ++j) {
        float v = R - sw[j] * xv[j];
        Bd[((size_t)j * TT + s) * DD + d] = __bfloat16_as_ushort(__float2bfloat16(v));
    }
}

// ============================================================
// Kernel 3: HMMA dual-GEMM, 512 threads (16 warps, 4x4 warp grid)
//   warp tile 32x32 per GEMM -> acc 64 regs/thread, ~110 regs total.
//   3-stage cp.async pipeline, BK=32, K=256 in 8 k-tiles.
// grid = 2 x 2 x 32 = 128 CTAs -> single wave, 1 CTA(16 warps)/SM.
// ============================================================
#define LDE 40                    // smem row stride in bf16 elems (80B)
#define TILE_ELE (128 * LDE)
#define STAGE_BYTES (4 * TILE_ELE * 2)   // V, A, Bd1, Bd2 = 40960 B
#define STAGES 3
#define SMEM_BYTES (STAGES * STAGE_BYTES)  // 122880

__device__ __forceinline__ void ldsm4(uint32_t* r, uint32_t addr) {
    asm volatile("ldmatrix.sync.aligned.m8n8.x4.shared.b16 {%0,%1,%2,%3}, [%4];"
                 : "=r"(r[0]), "=r"(r[1]), "=r"(r[2]), "=r"(r[3]) : "r"(addr));
}

__device__ __forceinline__ void mma_bf16(float* c, const uint32_t* a, const uint32_t* b) {
    asm volatile("mma.sync.aligned.m16n8k16.row.col.f32.bf16.bf16.f32 "
                 "{%0,%1,%2,%3},{%4,%5,%6,%7},{%8,%9},{%0,%1,%2,%3};"
                 : "+f"(c[0]), "+f"(c[1]), "+f"(c[2]), "+f"(c[3])
                 : "r"(a[0]), "r"(a[1]), "r"(a[2]), "r"(a[3]),
                   "r"(b[0]), "r"(b[1]));
}

__device__ __forceinline__ void cpa16(uint32_t dst, const void* src) {
    asm volatile("cp.async.cg.shared.global [%0], [%1], 16;\n"
                 :: "r"(dst), "l"(src) : "memory");
}

__device__ __forceinline__ float lg1p(float x) {
    if (fabsf(x) < 0.0625f)
        return x * fmaf(x, fmaf(x, fmaf(x, -0.25f, 0.33333333333f), -0.5f), 1.0f);
    return log1pf(x);
}

__global__ void __launch_bounds__(512, 1)
main_kernel(float* __restrict__ out) {
    extern __shared__ unsigned short dynsmem[];
    const uint32_t sbase = smem_u32(dynsmem);

    const int i  = blockIdx.z;
    const int t0 = blockIdx.y * 128;
    const int s0 = blockIdx.x * 128;

    const int tid  = threadIdx.x;
    const int lane = tid & 31;
    const int wid  = tid >> 5;   // 0..15
    const int wm   = wid & 3;    // warp row (t): 4 warps
    const int wn   = wid >> 2;   // warp col (s): 4 warps

    // global->smem mapping: each thread loads 1 row x 8 elems per operand tile
    const int row  = tid >> 2;          // 0..127
    const int c8   = (tid & 3) * 8;     // 0,8,16,24

    const unsigned short* pV  = g_VFb + ((size_t)(i * TT + t0 + row)) * DD + c8;
    const unsigned short* pA  = g_AFb + ((size_t)(i * TT + t0 + row)) * DD + c8;
    const unsigned short* pB1 = g_Bd1 + ((size_t)(i * TT + s0 + row)) * DD + c8;
    const unsigned short* pB2 = g_Bd2 + ((size_t)(i * TT + s0 + row)) * DD + c8;

    const uint32_t sob = (uint32_t)((row * LDE + c8) * 2);

    // acc[mf][n8][4]: warp tile 32x32 per GEMM (2 m-frags x 4 n8-frags)
    float acc1[2][4][4] = {};
    float acc2[2][4][4] = {};

    // ldmatrix per-thread relative byte offsets (within an operand tile)
    const uint32_t arel = (uint32_t)(((wm * 32 + (lane & 15)) * LDE + ((lane >> 4) * 8)) * 2);
    const uint32_t brel = (uint32_t)(((wn * 32 + (lane & 7) + ((lane & 16) >> 1)) * LDE
                                      + (((lane >> 3) & 1) * 8)) * 2);

#define ISSUE_STAGE(buf, k)                                                    \
    do {                                                                       \
        const uint32_t b_ = sbase + (uint32_t)(buf) * STAGE_BYTES;             \
        const int ko_ = (k) * 32;                                              \
        cpa16(b_ + 0 * (TILE_ELE * 2) + sob, pV + ko_);                        \
        cpa16(b_ + 1 * (TILE_ELE * 2) + sob, pA + ko_);                        \
        cpa16(b_ + 2 * (TILE_ELE * 2) + sob, pB1 + ko_);                       \
        cpa16(b_ + 3 * (TILE_ELE * 2) + sob, pB2 + ko_);                       \
        asm volatile("cp.async.commit_group;\n" ::: "memory");                 \
    } while (0)

    ISSUE_STAGE(0, 0);
    ISSUE_STAGE(1, 1);

#pragma unroll
    for (int k0 = 0; k0 < 8; ++k0) {
        asm volatile("cp.async.wait_group 1;\n" ::: "memory");
        __syncthreads();

        if (k0 + 2 < 8) {
            ISSUE_STAGE((k0 + 2) % STAGES, k0 + 2);
        } else {
            asm volatile("cp.async.commit_group;\n" ::: "memory");
        }

        const uint32_t bV  = sbase + (uint32_t)((k0 % STAGES)) * STAGE_BYTES;
        const uint32_t bA  = bV + 1 * (TILE_ELE * 2);
        const uint32_t bB1 = bV + 2 * (TILE_ELE * 2);
        const uint32_t bB2 = bV + 3 * (TILE_ELE * 2);

#pragma unroll
        for (int ks = 0; ks < 2; ++ks) {
            uint32_t av[2][4], aa[2][4];
            uint32_t b1[2][4], b2[2][4];
#pragma unroll
            for (int mf = 0; mf < 2; ++mf) {
                const uint32_t ao = (uint32_t)((mf * 16 * LDE + ks * 16) * 2);
                ldsm4(av[mf], bV + arel + ao);
                ldsm4(aa[mf], bA + arel + ao);
            }
#pragma unroll
            for (int nb = 0; nb < 2; ++nb) {
                const uint32_t bo = (uint32_t)((nb * 16 * LDE + ks * 16) * 2);
                ldsm4(b1[nb], bB1 + brel + bo);
                ldsm4(b2[nb], bB2 + brel + bo);
            }
#pragma unroll
            for (int mf = 0; mf < 2; ++mf) {
#pragma unroll
                for (int nb = 0; nb < 2; ++nb) {
                    mma_bf16(acc1[mf][nb * 2],     av[mf], &b1[nb][0]);
                    mma_bf16(acc1[mf][nb * 2 + 1], av[mf], &b1[nb][2]);
                    mma_bf16(acc2[mf][nb * 2],     aa[mf], &b2[nb][0]);
                    mma_bf16(acc2[mf][nb * 2 + 1], aa[mf], &b2[nb][2]);
                }
            }
        }
    }

    // ---- epilogue ----
    const float vi1 = g_vi1[i];
    const float vi2 = g_vi2[i];
    const float INV32 = 1.0f / 32.0f;
    const float TWO_LN32 = 6.931471805599453f;

#pragma unroll
    for (int mf = 0; mf < 2; ++mf) {
        const int rbase = t0 + wm * 32 + mf * 16 + (lane >> 2);
#pragma unroll
        for (int n8 = 0; n8 < 4; ++n8) {
            const int col = s0 + wn * 32 + n8 * 8 + (lane & 3) * 2;
            const float* c1 = acc1[mf][n8];
            const float* c2 = acc2[mf][n8];
            float2 o0, o1;
            o0.x = -(TWO_LN32 + lg1p(vi1 * c1[0] * INV32) + lg1p(vi2 * c2[0] * INV32));
            o0.y = -(TWO_LN32 + lg1p(vi1 * c1[1] * INV32) + lg1p(vi2 * c2[1] * INV32));
            o1.x = -(TWO_LN32 + lg1p(vi1 * c1[2] * INV32) + lg1p(vi2 * c2[2] * INV32));
            o1.y = -(TWO_LN32 + lg1p(vi1 * c1[3] * INV32) + lg1p(vi2 * c2[3] * INV32));
            *(float2*)&out[((size_t)(i * TT + rbase)) * TT + col] = o0;
            *(float2*)&out[((size_t)(i * TT + rbase + 8)) * TT + col] = o1;
        }
    }
}

// ============================================================
extern "C" void kernel_launch(void* const* d_in, const int* in_sizes, int n_in,
                              void* d_out, int out_size) {
    // metadata order: pre_VF, pre_AF, back_VF, back_AF (only back_* are used)
    const float* VF = (const float*)d_in[2];
    const float* AF = (const float*)d_in[3];
    float* out = (float*)d_out;
    (void)in_sizes; (void)n_in; (void)out_size;

    cudaFuncSetAttribute(main_kernel,
                         cudaFuncAttributeMaxDynamicSharedMemorySize, SMEM_BYTES);

    stats1_kernel<<<256, 256>>>(VF, AF);
    stats2_kernel<<<64, 256>>>();
    build_kernel<<<dim3(256, 2), 256>>>();
    main_kernel<<<dim3(2, 2, 32), 512, SMEM_BYTES>>>(out);
}